// round 3
// baseline (speedup 1.0000x reference)
#include <cuda_runtime.h>

// Problem constants
#define NS   65536
#define KEXP 8
#define DIN  74
#define WID  64
#define DOUT 32
#define TILE 256
#define NT   512
#define MAXTILES (NS / TILE + KEXP)
#define NSCAT 256

// smem (floats): Xs[74][256] + Hs[64][256] + W0d[74][128] + W1d[64][128] + W2[64][32] + b0/b1/b2
#define W0D (DIN * 128)
#define W1D (WID * 128)
#define W2S (WID * DOUT)
#define SMEM_FLOATS (DIN*TILE + WID*TILE + W0D + W1D + W2S + WID + WID + DOUT)
#define SMEM_BYTES  (SMEM_FLOATS * 4 + TILE * 4)   // + sids

typedef unsigned long long u64;

// ---------------- device scratch ----------------
__device__ int g_hist[KEXP];           // zero-init at load; k_scan re-zeroes after use
__device__ int g_offs[KEXP + 1];
__device__ int g_cursor[KEXP];
__device__ int g_order[NS];

// ---------------- packed fp32x2 helpers (sm_103a) ----------------
__device__ __forceinline__ u64 pk2(float x, float y) {
    u64 r; asm("mov.b64 %0, {%1, %2};" : "=l"(r) : "f"(x), "f"(y)); return r;
}
__device__ __forceinline__ void upk2(u64 p, float& x, float& y) {
    asm("mov.b64 {%0, %1}, %2;" : "=f"(x), "=f"(y) : "l"(p));
}
__device__ __forceinline__ void fma2(u64& c, u64 a, u64 b) {
    asm("fma.rn.f32x2 %0, %1, %2, %0;" : "+l"(c) : "l"(a), "l"(b));
}

// ---------------- bucketing ----------------
__global__ void k_hist(const int* __restrict__ idxs) {
    __shared__ int sh[KEXP];
    if (threadIdx.x < KEXP) sh[threadIdx.x] = 0;
    __syncthreads();
    atomicAdd(&sh[idxs[blockIdx.x * 256 + threadIdx.x]], 1);
    __syncthreads();
    if (threadIdx.x < KEXP) atomicAdd(&g_hist[threadIdx.x], sh[threadIdx.x]);
}

__global__ void k_scan() {
    int acc = 0;
    for (int e = 0; e < KEXP; e++) {
        g_offs[e] = acc; g_cursor[e] = acc;
        acc += g_hist[e];
        g_hist[e] = 0;
    }
    g_offs[KEXP] = acc;
}

__global__ void k_scatter(const int* __restrict__ idxs) {
    __shared__ int s_loc[KEXP];
    __shared__ int s_base[KEXP];
    if (threadIdx.x < KEXP) s_loc[threadIdx.x] = 0;
    __syncthreads();
    int i = blockIdx.x * 256 + threadIdx.x;
    int e = idxs[i];
    int r = atomicAdd(&s_loc[e], 1);
    __syncthreads();
    if (threadIdx.x < KEXP)
        s_base[threadIdx.x] = atomicAdd(&g_cursor[threadIdx.x], s_loc[threadIdx.x]);
    __syncthreads();
    g_order[s_base[e] + r] = i;
}

// ---------------- weight staging ----------------
// plain copy
__device__ __forceinline__ void copy_plain(float* __restrict__ dst, const float* __restrict__ src,
                                           int n, int tid) {
    for (int i = tid; i < n; i += NT) dst[i] = src[i];
}
// duplicated copy: dst[k][2c] = dst[k][2c+1] = src[k][c]   (src [KD][64] -> dst [KD][128])
__device__ __forceinline__ void copy_dup(float* __restrict__ dst, const float* __restrict__ src,
                                         int n, int tid) {
    for (int i = tid; i < n; i += NT) {
        float v = src[i];
        int k = i >> 6, c = i & 63;
        *(float2*)&dst[k * 128 + 2 * c] = make_float2(v, v);
    }
}

// ---------------- GEMM: [256 x KD] @ [KD x 64] + bias, relu -> O[64][256] ----------------
// A k-major [KD][256]; Wd duplicated [KD][128]; thread: 4 contiguous samples x 8 cols.
template <int KD>
__device__ __forceinline__ void gemm_relu(const float* __restrict__ A,
                                          const float* __restrict__ Wd,
                                          const float* __restrict__ bias,
                                          float* __restrict__ O,
                                          int s0, int c0) {
    u64 acc[2][8];
#pragma unroll
    for (int j = 0; j < 8; j++) {
        float bv = bias[c0 + j];
        u64 b = pk2(bv, bv);
        acc[0][j] = b; acc[1][j] = b;
    }
#pragma unroll 2
    for (int k = 0; k < KD; k++) {
        ulonglong2 av = *(const ulonglong2*)&A[k * TILE + s0];      // LDS.128, 16B lane stride: conflict-free
        ulonglong2 w0 = *(const ulonglong2*)&Wd[k * 128 + 2 * c0];      // broadcast
        ulonglong2 w1 = *(const ulonglong2*)&Wd[k * 128 + 2 * c0 + 4];
        ulonglong2 w2 = *(const ulonglong2*)&Wd[k * 128 + 2 * c0 + 8];
        ulonglong2 w3 = *(const ulonglong2*)&Wd[k * 128 + 2 * c0 + 12];
        u64 b[8] = { w0.x, w0.y, w1.x, w1.y, w2.x, w2.y, w3.x, w3.y };
#pragma unroll
        for (int j = 0; j < 8; j++) {
            fma2(acc[0][j], av.x, b[j]);
            fma2(acc[1][j], av.y, b[j]);
        }
    }
#pragma unroll
    for (int j = 0; j < 8; j++) {
        float x0, x1, x2, x3;
        upk2(acc[0][j], x0, x1);
        upk2(acc[1][j], x2, x3);
        *(float4*)&O[(c0 + j) * TILE + s0] =
            make_float4(fmaxf(x0, 0.f), fmaxf(x1, 0.f), fmaxf(x2, 0.f), fmaxf(x3, 0.f));  // STS.128 conflict-free
    }
}

// ---------------- final layer: [256 x 64] @ [64 x 32] + bias -> global scatter ----------------
__device__ __forceinline__ void gemm_out(const float* __restrict__ A, const float* __restrict__ W,
                                         const float* __restrict__ bias, float* __restrict__ out,
                                         const int* __restrict__ sids, int cnt, int s0, int c0) {
    u64 acc[2][4];
#pragma unroll
    for (int j = 0; j < 4; j++) {
        float bv = bias[c0 + j];
        u64 b = pk2(bv, bv);
        acc[0][j] = b; acc[1][j] = b;
    }
#pragma unroll 2
    for (int k = 0; k < WID; k++) {
        ulonglong2 av = *(const ulonglong2*)&A[k * TILE + s0];
        float4 w = *(const float4*)&W[k * DOUT + c0];
        u64 b[4] = { pk2(w.x, w.x), pk2(w.y, w.y), pk2(w.z, w.z), pk2(w.w, w.w) };
#pragma unroll
        for (int j = 0; j < 4; j++) {
            fma2(acc[0][j], av.x, b[j]);
            fma2(acc[1][j], av.y, b[j]);
        }
    }
#pragma unroll
    for (int p = 0; p < 2; p++) {
        float lo[4], hi[4];
#pragma unroll
        for (int j = 0; j < 4; j++) upk2(acc[p][j], lo[j], hi[j]);
        int r0 = s0 + 2 * p;
        if (r0 < cnt)
            *(float4*)&out[(size_t)sids[r0] * DOUT + c0] = make_float4(lo[0], lo[1], lo[2], lo[3]);
        if (r0 + 1 < cnt)
            *(float4*)&out[(size_t)sids[r0 + 1] * DOUT + c0] = make_float4(hi[0], hi[1], hi[2], hi[3]);
    }
}

// ---------------- fused MLP kernel ----------------
__global__ void __launch_bounds__(NT) k_mlp(
    const float* __restrict__ positions, const float* __restrict__ viewdirs,
    const float* __restrict__ features,
    const float* __restrict__ W0, const float* __restrict__ b0,
    const float* __restrict__ W1, const float* __restrict__ b1,
    const float* __restrict__ W2, const float* __restrict__ b2,
    float* __restrict__ out) {
    extern __shared__ float sm[];
    float* Xs  = sm;                        // [74][256], reused as layer-1 output
    float* Hs  = Xs + DIN * TILE;           // [64][256]
    float* W0d = Hs + WID * TILE;           // [74][128] duplicated
    float* W1d = W0d + W0D;                 // [64][128] duplicated
    float* W2s = W1d + W1D;                 // [64][32]
    float* B0  = W2s + W2S;
    float* B1  = B0 + WID;
    float* B2  = B1 + WID;
    int* sids  = (int*)(B2 + DOUT);
    int tid = threadIdx.x;

    // blockIdx -> (expert, local tile)
    int e = -1, lt = 0;
    {
        int b = blockIdx.x, acc = 0;
#pragma unroll
        for (int i = 0; i < KEXP; i++) {
            int tiles = (g_offs[i + 1] - g_offs[i] + TILE - 1) / TILE;
            if (e < 0 && b < acc + tiles) { e = i; lt = b - acc; }
            acc += tiles;
        }
    }
    if (e < 0) return;
    int base = g_offs[e] + lt * TILE;
    int cnt = min(TILE, g_offs[e + 1] - base);

    // ---- stage weights (all 512 threads) ----
    copy_dup(W0d, W0 + e * DIN * WID, DIN * WID, tid);
    copy_dup(W1d, W1 + e * WID * WID, WID * WID, tid);
    copy_plain(W2s, W2 + e * W2S, W2S, tid);
    if (tid < WID)  B0[tid] = b0[e * WID + tid];
    if (tid >= WID && tid < 2 * WID)   B1[tid - WID] = b1[e * WID + tid - WID];
    if (tid >= 2 * WID && tid < 2 * WID + DOUT) B2[tid - 2 * WID] = b2[e * DOUT + tid - 2 * WID];

    // ---- gather + encode (threads 0..255, one sample each) ----
    if (tid < TILE) {
        int n = g_order[base + min(tid, cnt - 1)];   // pad partial tiles with a valid row
        sids[tid] = n;
        const float4* f4 = (const float4*)(features + (size_t)n * 32);
#pragma unroll
        for (int i = 0; i < 8; i++) {
            float4 f = f4[i];
            Xs[(i * 4 + 0) * TILE + tid] = f.x;
            Xs[(i * 4 + 1) * TILE + tid] = f.y;
            Xs[(i * 4 + 2) * TILE + tid] = f.z;
            Xs[(i * 4 + 3) * TILE + tid] = f.w;
        }
        float p0 = positions[n * 3], p1 = positions[n * 3 + 1], p2 = positions[n * 3 + 2];
        Xs[32 * TILE + tid] = p0; Xs[33 * TILE + tid] = p1; Xs[34 * TILE + tid] = p2;
#pragma unroll
        for (int s = 0; s < 2; s++) {
            float sc = (float)(1 << s);
            float v0 = p0 * sc, v1 = p1 * sc, v2 = p2 * sc;
            Xs[(35 + s * 3) * TILE + tid] = __sinf(v0);
            Xs[(36 + s * 3) * TILE + tid] = __sinf(v1);
            Xs[(37 + s * 3) * TILE + tid] = __sinf(v2);
            Xs[(41 + s * 3) * TILE + tid] = __cosf(v0);
            Xs[(42 + s * 3) * TILE + tid] = __cosf(v1);
            Xs[(43 + s * 3) * TILE + tid] = __cosf(v2);
        }
        float q0 = viewdirs[n * 3], q1 = viewdirs[n * 3 + 1], q2 = viewdirs[n * 3 + 2];
        Xs[47 * TILE + tid] = q0; Xs[48 * TILE + tid] = q1; Xs[49 * TILE + tid] = q2;
#pragma unroll
        for (int s = 0; s < 4; s++) {
            float sc = (float)(1 << s);
            float v0 = q0 * sc, v1 = q1 * sc, v2 = q2 * sc;
            Xs[(50 + s * 3) * TILE + tid] = __sinf(v0);
            Xs[(51 + s * 3) * TILE + tid] = __sinf(v1);
            Xs[(52 + s * 3) * TILE + tid] = __sinf(v2);
            Xs[(62 + s * 3) * TILE + tid] = __cosf(v0);
            Xs[(63 + s * 3) * TILE + tid] = __cosf(v1);
            Xs[(64 + s * 3) * TILE + tid] = __cosf(v2);
        }
    }
    __syncthreads();

    // thread tile: warp w (0..15): col group cg = w&7 (8 cols), sample half sh = w>>3
    int lane = tid & 31;
    int w = tid >> 5;
    int c0 = (w & 7) * 8;
    int s0 = (w >> 3) * 128 + lane * 4;

    gemm_relu<DIN>(Xs, W0d, B0, Hs, s0, c0);
    __syncthreads();
    gemm_relu<WID>(Hs, W1d, B1, Xs, s0, c0);
    __syncthreads();

    int c0o = (w & 7) * 4;   // 8 groups x 4 cols = 32
    gemm_out(Xs, W2s, B2, out, sids, cnt, s0, c0o);
}

// ---------------- launch ----------------
extern "C" void kernel_launch(void* const* d_in, const int* in_sizes, int n_in,
                              void* d_out, int out_size) {
    (void)in_sizes; (void)n_in; (void)out_size;
    const int*   idxs      = (const int*)d_in[0];
    const float* positions = (const float*)d_in[1];
    const float* viewdirs  = (const float*)d_in[2];
    const float* features  = (const float*)d_in[3];
    const float* W0 = (const float*)d_in[4];
    const float* b0 = (const float*)d_in[5];
    const float* W1 = (const float*)d_in[6];
    const float* b1 = (const float*)d_in[7];
    const float* W2 = (const float*)d_in[8];
    const float* b2 = (const float*)d_in[9];
    float* out = (float*)d_out;

    cudaFuncSetAttribute(k_mlp, cudaFuncAttributeMaxDynamicSharedMemorySize, SMEM_BYTES);

    k_hist<<<NSCAT, 256>>>(idxs);
    k_scan<<<1, 1>>>();
    k_scatter<<<NSCAT, 256>>>(idxs);
    k_mlp<<<MAXTILES, NT, SMEM_BYTES>>>(positions, viewdirs, features,
                                        W0, b0, W1, b1, W2, b2, out);
}